// round 16
// baseline (speedup 1.0000x reference)
#include <cuda_runtime.h>
#include <cuda_fp16.h>
#include <math.h>
#include <stdint.h>

#define B_    8
#define KB_   16
#define SEQ_  512
#define HID_  768
#define NPAIR 128
#define STILES 8                 // max 64-row s-tiles
#define KTILES 4                 // max 128-col k-tiles
#define NEG_BIG (-3.0e38f)
#define NGRP  32                 // norm blocks per batch row

// ---------------- scratch (static device arrays; no allocation) ----------------
__device__ __align__(256) __half g_qn[B_ * SEQ_ * HID_];
__device__ __align__(256) __half g_kn[KB_ * SEQ_ * HID_];
__device__ int g_qidx[B_ * SEQ_];
__device__ int g_kidx[KB_ * SEQ_];
__device__ int g_qcnt[B_];
__device__ int g_kcnt[KB_];
__device__ float g_dtab[SEQ_];
#define MLR_N (NPAIR * STILES * KTILES * 64)
__device__ float g_m[MLR_N];
__device__ float g_l[MLR_N];
__device__ float g_r[MLR_N];

// ---------------- helpers ----------------
__device__ __forceinline__ uint32_t smem_u32(const void* p) {
    uint32_t a;
    asm("{ .reg .u64 t; cvta.to.shared.u64 t, %1; cvt.u32.u64 %0, t; }" : "=r"(a) : "l"(p));
    return a;
}
#define SWZ(off) ((off) ^ (((off) >> 3) & 0x70))

__device__ __forceinline__ void cp16(uint32_t saddr, const void* g) {
    asm volatile("cp.async.cg.shared.global [%0], [%1], 16;" :: "r"(saddr), "l"(g));
}
#define CP_COMMIT() asm volatile("cp.async.commit_group;" ::: "memory")
#define CP_WAIT0()  asm volatile("cp.async.wait_group 0;" ::: "memory")

#define LDSM4(r0, r1, r2, r3, addr) \
    asm volatile("ldmatrix.sync.aligned.m8n8.x4.shared.b16 {%0,%1,%2,%3}, [%4];" \
        : "=r"(r0), "=r"(r1), "=r"(r2), "=r"(r3) : "r"(addr))

#define MMA16816(d, a, b) \
    asm volatile("mma.sync.aligned.m16n8k16.row.col.f32.f16.f16.f32 " \
        "{%0,%1,%2,%3}, {%4,%5,%6,%7}, {%8,%9}, {%0,%1,%2,%3};" \
        : "+f"((d)[0]), "+f"((d)[1]), "+f"((d)[2]), "+f"((d)[3]) \
        : "r"((a)[0]), "r"((a)[1]), "r"((a)[2]), "r"((a)[3]), \
          "r"((b)[0]), "r"((b)[1]))

// fast exp on FMA/ALU pipes (x <= 0); avoids the MUFU throughput wall.
__device__ __forceinline__ float fexp(float x) {
    float t = fmaxf(x * 1.4426950408889634f, -126.0f);
    float z = t + 12582912.0f;
    float fl = z - 12582912.0f;
    float f = t - fl;
    int n = __float_as_int(z) - 0x4B400000;
    float p = 1.3333558146e-3f;
    p = fmaf(p, f, 9.6181291056e-3f);
    p = fmaf(p, f, 5.5504108664e-2f);
    p = fmaf(p, f, 2.4022650696e-1f);
    p = fmaf(p, f, 6.9314718056e-1f);
    p = fmaf(p, f, 1.0f);
    return __int_as_float((n + 127) << 23) * p;
}

// ---------------- smem layout (dynamic, li_tile) ----------------
#define OFF_DTAB  0                     // 512 floats (2048B)
#define OFF_QIDX  2048                  // 64 ints
#define OFF_KIDX  2304                  // 128 ints
#define OFF_EPI   2816                  // m[256], l[256], r[256] floats (3072B)
#define OFF_Q0    6144                  // 2 x 8KB Q stage
#define OFF_K0    22528                 // 2 x 16KB K stage
#define SMEM_TOTAL 55296                // 54KB -> 3 CTAs/SM

// ---------------- kernel P: norm (with replicated compaction) + dtab ----------
__global__ __launch_bounds__(512) void prep(const float* __restrict__ qin,
                                            const float* __restrict__ kin,
                                            const int* __restrict__ qm,
                                            const int* __restrict__ kmm,
                                            const float* __restrict__ alpha_p) {
    const int blk = blockIdx.x;
    const int tid = threadIdx.x;
    if (blk == 24 * NGRP) {
        float ar = alpha_p[0];
        float alpha = ar > 0.f ? ar : 0.01f * ar;    // leaky_relu
        g_dtab[tid] = __expf(-alpha * (float)tid);
        return;
    }
    const int b = blk / NGRP;
    const int g = blk % NGRP;
    const int which = b >= 8;
    const int i = which ? b - 8 : b;
    const int* msk = which ? kmm + i * SEQ_ : qm + i * SEQ_;

    __shared__ int idxS[SEQ_];
    __shared__ int wcnt[16], wpre[16];
    __shared__ int cntS;
    const int warp = tid >> 5, lane = tid & 31;

    int v = msk[tid] != 0;
    unsigned bl = __ballot_sync(0xffffffffu, v);
    if (lane == 0) wcnt[warp] = __popc(bl);
    __syncthreads();
    if (tid == 0) {
        int s = 0;
        #pragma unroll
        for (int w = 0; w < 16; w++) { wpre[w] = s; s += wcnt[w]; }
        cntS = s;
    }
    __syncthreads();
    if (v) idxS[wpre[warp] + __popc(bl & ((1u << lane) - 1))] = tid;
    __syncthreads();
    const int cnt = cntS;

    if (g == 0) {
        if (tid < cnt) (which ? g_kidx : g_qidx)[i * SEQ_ + tid] = idxS[tid];
        if (tid == 0)  (which ? g_kcnt : g_qcnt)[i] = cnt;
    }

    const int sp = g * 16 + warp;
    if (sp >= cnt) return;
    const float* in = (which ? kin : qin) + (long)i * SEQ_ * HID_;
    __half* outb = (which ? g_kn : g_qn) + (long)i * SEQ_ * HID_;

    const float4* src = (const float4*)(in + (long)idxS[sp] * HID_);
    float4 vv[6];
    float s = 0.f;
    #pragma unroll
    for (int k = 0; k < 6; k++) {
        vv[k] = src[lane + 32 * k];
        s += vv[k].x * vv[k].x + vv[k].y * vv[k].y + vv[k].z * vv[k].z + vv[k].w * vv[k].w;
    }
    #pragma unroll
    for (int o = 16; o; o >>= 1) s += __shfl_xor_sync(0xffffffffu, s, o);
    float sc = 1.0f / fmaxf(sqrtf(s), 1e-12f);
    uint2* dst = (uint2*)(outb + (long)sp * HID_);
    #pragma unroll
    for (int k = 0; k < 6; k++) {
        __half2 h0 = __floats2half2_rn(vv[k].x * sc, vv[k].y * sc);
        __half2 h1 = __floats2half2_rn(vv[k].z * sc, vv[k].w * sc);
        uint2 u;
        u.x = *reinterpret_cast<uint32_t*>(&h0);
        u.y = *reinterpret_cast<uint32_t*>(&h1);
        dst[lane + 32 * k] = u;
    }
}

// ---------------- kernel 1: one (pair, 64-row stile, 128-col ktile) per CTA ----
// 256 threads, 8 warps in 2(M) x 4(N); warp tile 32x32; 3 CTAs/SM.
__global__ __launch_bounds__(256, 3) void li_tile() {
    extern __shared__ char sm[];
    const uint32_t sb = smem_u32(sm);
    const int tid = threadIdx.x, wid = tid >> 5, lane = tid & 31;
    const int wr = wid >> 2, wc = wid & 3;
    const int pair = blockIdx.z;
    const int i = pair >> 4, j = pair & 15;
    const int s0 = blockIdx.y * 64;
    const int t0 = blockIdx.x * 128;

    const int qcnt = g_qcnt[i];
    const int kcnt = g_kcnt[j];
    if (s0 >= qcnt || t0 >= kcnt) return;

    float* dtab  = (float*)(sm + OFF_DTAB);
    int*   qidxS = (int*)(sm + OFF_QIDX);
    int*   kidxS = (int*)(sm + OFF_KIDX);
    float* epi   = (float*)(sm + OFF_EPI);

    // staging row maps: Q 8KB = 512x16B (2 iters), K 16KB = 1024x16B (4 iters)
    int qr[2], kr[4];
    #pragma unroll
    for (int it = 0; it < 2; it++)
        qr[it] = min(s0 + ((tid + it * 256) >> 3), qcnt - 1);
    #pragma unroll
    for (int it = 0; it < 4; it++)
        kr[it] = min(t0 + ((tid + it * 256) >> 3), kcnt - 1);
    const int seg = tid & 7;

    const uint4* qsrc = (const uint4*)g_qn + (long)i * SEQ_ * 96;
    const uint4* ksrc = (const uint4*)g_kn + (long)j * SEQ_ * 96;

    // stage chunk 0
    {
        uint32_t qb = sb + OFF_Q0, kb = sb + OFF_K0;
        #pragma unroll
        for (int it = 0; it < 2; it++) {
            int r = (tid + it * 256) >> 3;
            cp16(qb + SWZ((uint32_t)(r * 128 + seg * 16)), qsrc + qr[it] * 96 + seg);
        }
        #pragma unroll
        for (int it = 0; it < 4; it++) {
            int r = (tid + it * 256) >> 3;
            cp16(kb + SWZ((uint32_t)(r * 128 + seg * 16)), ksrc + kr[it] * 96 + seg);
        }
        CP_COMMIT();
    }

    {
        dtab[tid]       = g_dtab[tid];
        dtab[tid + 256] = g_dtab[tid + 256];
        if (tid < 64)  qidxS[tid] = g_qidx[i * SEQ_ + min(s0 + tid, qcnt - 1)];
        if (tid < 128) kidxS[tid] = g_kidx[j * SEQ_ + min(t0 + tid, kcnt - 1)];
    }

    float acc[2][4][4];
    #pragma unroll
    for (int a = 0; a < 2; a++)
        #pragma unroll
        for (int b = 0; b < 4; b++)
            #pragma unroll
            for (int e = 0; e < 4; e++) acc[a][b][e] = 0.f;
    __syncthreads();

    for (int kc = 0; kc < 12; kc++) {
        const int b = kc & 1;
        CP_WAIT0();
        __syncthreads();
        if (kc < 11) {
            uint32_t qb = sb + OFF_Q0 + (b ^ 1) * 8192;
            uint32_t kb = sb + OFF_K0 + (b ^ 1) * 16384;
            #pragma unroll
            for (int it = 0; it < 2; it++) {
                int r = (tid + it * 256) >> 3;
                cp16(qb + SWZ((uint32_t)(r * 128 + seg * 16)), qsrc + qr[it] * 96 + (kc + 1) * 8 + seg);
            }
            #pragma unroll
            for (int it = 0; it < 4; it++) {
                int r = (tid + it * 256) >> 3;
                cp16(kb + SWZ((uint32_t)(r * 128 + seg * 16)), ksrc + kr[it] * 96 + (kc + 1) * 8 + seg);
            }
            CP_COMMIT();
        }
        const uint32_t qbase = sb + OFF_Q0 + b * 8192;
        const uint32_t kbase = sb + OFF_K0 + b * 16384;
        #pragma unroll
        for (int ks = 0; ks < 4; ks++) {
            uint32_t afr[2][4];
            #pragma unroll
            for (int mt = 0; mt < 2; mt++) {
                int rowA = wr * 32 + mt * 16 + (lane & 7) + ((lane >> 3) & 1) * 8;
                int kcol = ks * 16 + (lane >> 4) * 8;
                uint32_t ad = qbase + SWZ((uint32_t)(rowA * 128 + kcol * 2));
                LDSM4(afr[mt][0], afr[mt][1], afr[mt][2], afr[mt][3], ad);
            }
            uint32_t bfr[4][2];
            #pragma unroll
            for (int np = 0; np < 2; np++) {
                int nrow = wc * 32 + (np * 2 + (lane >> 4)) * 8 + (lane & 7);
                int kcol = ks * 16 + ((lane >> 3) & 1) * 8;
                uint32_t ad = kbase + SWZ((uint32_t)(nrow * 128 + kcol * 2));
                LDSM4(bfr[np * 2][0], bfr[np * 2][1],
                      bfr[np * 2 + 1][0], bfr[np * 2 + 1][1], ad);
            }
            #pragma unroll
            for (int mt = 0; mt < 2; mt++)
                #pragma unroll
                for (int nt = 0; nt < 4; nt++)
                    MMA16816(acc[mt][nt], afr[mt], bfr[nt]);
        }
    }

    // ---- per-tile softmax partials ----
    float* mS = epi;          // [4][64]
    float* lS = epi + 256;
    float* rS = epi + 512;

    #pragma unroll
    for (int mt = 0; mt < 2; mt++) {
        #pragma unroll
        for (int h = 0; h < 2; h++) {
            int rowl = wr * 32 + mt * 16 + h * 8 + (lane >> 2);
            int sO = qidxS[rowl];
            float lg[8];
            float bm = NEG_BIG;
            #pragma unroll
            for (int nt = 0; nt < 4; nt++) {
                #pragma unroll
                for (int e = 0; e < 2; e++) {
                    int tl = wc * 32 + nt * 8 + (lane & 3) * 2 + e;
                    float c = acc[mt][nt][h * 2 + e];
                    float w = dtab[abs(sO - kidxS[tl])];
                    float L = (t0 + tl < kcnt) ? c * w : NEG_BIG;
                    lg[nt * 2 + e] = L;
                    bm = fmaxf(bm, L);
                }
            }
            bm = fmaxf(bm, __shfl_xor_sync(0xffffffffu, bm, 1));
            bm = fmaxf(bm, __shfl_xor_sync(0xffffffffu, bm, 2));
            float lv = 0.f, rv = 0.f;
            #pragma unroll
            for (int nt = 0; nt < 4; nt++) {
                #pragma unroll
                for (int e = 0; e < 2; e++) {
                    float p = fexp(lg[nt * 2 + e] - bm);
                    lv += p;
                    rv += p * acc[mt][nt][h * 2 + e];
                }
            }
            lv += __shfl_xor_sync(0xffffffffu, lv, 1);
            lv += __shfl_xor_sync(0xffffffffu, lv, 2);
            rv += __shfl_xor_sync(0xffffffffu, rv, 1);
            rv += __shfl_xor_sync(0xffffffffu, rv, 2);
            if ((lane & 3) == 0) {
                mS[wc * 64 + rowl] = bm;
                lS[wc * 64 + rowl] = lv;
                rS[wc * 64 + rowl] = rv;
            }
        }
    }
    __syncthreads();

    // merge the 4 N-strips, write per-row partials
    if (tid < 64) {
        float m0 = mS[tid],       m1 = mS[64 + tid];
        float m2 = mS[128 + tid], m3 = mS[192 + tid];
        float ma = fmaxf(m0, m1), mb = fmaxf(m2, m3);
        float mm = fmaxf(ma, mb);
        float e0 = fexp(m0 - mm), e1 = fexp(m1 - mm);
        float e2 = fexp(m2 - mm), e3 = fexp(m3 - mm);
        float ll = lS[tid] * e0 + lS[64 + tid] * e1 + lS[128 + tid] * e2 + lS[192 + tid] * e3;
        float rr = rS[tid] * e0 + rS[64 + tid] * e1 + rS[128 + tid] * e2 + rS[192 + tid] * e3;
        long o = ((((long)pair * STILES + blockIdx.y) * KTILES + blockIdx.x) << 6) + tid;
        g_m[o] = mm; g_l[o] = ll; g_r[o] = rr;
    }
}

// ---------------- kernel 2: merge + rowsum -> out[B,KB] ----------------
// grid NPAIR, 512 threads = (stile 0..7, row 0..63); parallel kt loads.
__global__ __launch_bounds__(512) void li_combine(float* __restrict__ out) {
    const int pair = blockIdx.x;
    const int i = pair >> 4, j = pair & 15;
    const int qcnt = g_qcnt[i], kcnt = g_kcnt[j];
    const int ktiles = (kcnt + 127) >> 7;
    const int tid = threadIdx.x;
    const int st = tid >> 6, row = tid & 63;
    const int lane = tid & 31;

    float val = 0.f;
    if (st * 64 + row < qcnt) {
        long base = ((((long)pair * STILES + st) * KTILES) << 6) + row;
        float m[4], l[4], r[4];
        #pragma unroll
        for (int kt = 0; kt < KTILES; kt++) {
            bool v = kt < ktiles;
            long o = base + ((long)kt << 6);
            m[kt] = v ? g_m[o] : NEG_BIG;
            l[kt] = v ? g_l[o] : 0.f;
            r[kt] = v ? g_r[o] : 0.f;
        }
        float ma = fmaxf(m[0], m[1]);
        float ea0 = fexp(m[0] - ma), ea1 = fexp(m[1] - ma);
        float la = l[0] * ea0 + l[1] * ea1;
        float ra = r[0] * ea0 + r[1] * ea1;
        float mb = fmaxf(m[2], m[3]);
        float eb0 = fexp(m[2] - mb), eb1 = fexp(m[3] - mb);
        float lb = l[2] * eb0 + l[3] * eb1;
        float rb = r[2] * eb0 + r[3] * eb1;
        float mf = fmaxf(ma, mb);
        float ef0 = fexp(ma - mf), ef1 = fexp(mb - mf);
        float lf = la * ef0 + lb * ef1;
        float rf = ra * ef0 + rb * ef1;
        val = (lf > 0.f) ? rf / lf : 0.f;
    }
    #pragma unroll
    for (int o = 16; o; o >>= 1) val += __shfl_xor_sync(0xffffffffu, val, o);
    __shared__ float w16[16];
    if (lane == 0) w16[tid >> 5] = val;
    __syncthreads();
    if (tid < 16) {
        float v = w16[tid];
        #pragma unroll
        for (int o = 8; o; o >>= 1) v += __shfl_xor_sync(0xffffu, v, o);
        if (tid == 0) out[pair] = v;
    }
}

// ---------------- launch ----------------
extern "C" void kernel_launch(void* const* d_in, const int* in_sizes, int n_in,
                              void* d_out, int out_size) {
    const float* qe    = (const float*)d_in[0];   // [8,512,768]
    const float* ke    = (const float*)d_in[1];   // [16,512,768]
    const float* alpha = (const float*)d_in[2];   // scalar
    const int*   qm    = (const int*)d_in[3];     // [8,512]
    const int*   kmm   = (const int*)d_in[4];     // [16,512]
    float* out = (float*)d_out;                   // [8,16]

    cudaFuncSetAttribute(li_tile, cudaFuncAttributeMaxDynamicSharedMemorySize, SMEM_TOTAL);

    prep<<<24 * NGRP + 1, 512>>>(qe, ke, qm, kmm, alpha);
    dim3 grid(KTILES, STILES, NPAIR);
    li_tile<<<grid, 256, SMEM_TOTAL>>>();
    li_combine<<<NPAIR, 512>>>(out);
}

// round 17
// speedup vs baseline: 1.0038x; 1.0038x over previous
#include <cuda_runtime.h>
#include <cuda_fp16.h>
#include <math.h>
#include <stdint.h>

#define B_    8
#define KB_   16
#define SEQ_  512
#define HID_  768
#define NPAIR 128
#define STILES 8                 // max 64-row s-tiles
#define KTILES 4                 // max 128-col k-tiles
#define NEG_BIG (-3.0e38f)
#define NGRP  32                 // norm blocks per batch row

// ---------------- scratch (static device arrays; no allocation) ----------------
__device__ __align__(256) __half g_qn[B_ * SEQ_ * HID_];
__device__ __align__(256) __half g_kn[KB_ * SEQ_ * HID_];
__device__ int g_qidx[B_ * SEQ_];
__device__ int g_kidx[KB_ * SEQ_];
__device__ int g_qcnt[B_];
__device__ int g_kcnt[KB_];
__device__ float g_dtab[SEQ_];
#define MLR_N (NPAIR * STILES * KTILES * 64)
__device__ float g_m[MLR_N];
__device__ float g_l[MLR_N];
__device__ float g_r[MLR_N];

// ---------------- helpers ----------------
__device__ __forceinline__ uint32_t smem_u32(const void* p) {
    uint32_t a;
    asm("{ .reg .u64 t; cvta.to.shared.u64 t, %1; cvt.u32.u64 %0, t; }" : "=r"(a) : "l"(p));
    return a;
}
#define SWZ(off) ((off) ^ (((off) >> 3) & 0x70))

__device__ __forceinline__ void cp16(uint32_t saddr, const void* g) {
    asm volatile("cp.async.cg.shared.global [%0], [%1], 16;" :: "r"(saddr), "l"(g));
}
#define CP_COMMIT() asm volatile("cp.async.commit_group;" ::: "memory")
#define CP_WAIT0()  asm volatile("cp.async.wait_group 0;" ::: "memory")

#define LDSM4(r0, r1, r2, r3, addr) \
    asm volatile("ldmatrix.sync.aligned.m8n8.x4.shared.b16 {%0,%1,%2,%3}, [%4];" \
        : "=r"(r0), "=r"(r1), "=r"(r2), "=r"(r3) : "r"(addr))

#define MMA16816(d, a, b) \
    asm volatile("mma.sync.aligned.m16n8k16.row.col.f32.f16.f16.f32 " \
        "{%0,%1,%2,%3}, {%4,%5,%6,%7}, {%8,%9}, {%0,%1,%2,%3};" \
        : "+f"((d)[0]), "+f"((d)[1]), "+f"((d)[2]), "+f"((d)[3]) \
        : "r"((a)[0]), "r"((a)[1]), "r"((a)[2]), "r"((a)[3]), \
          "r"((b)[0]), "r"((b)[1]))

// fast exp on FMA/ALU pipes (x <= 0); avoids the MUFU throughput wall.
__device__ __forceinline__ float fexp(float x) {
    float t = fmaxf(x * 1.4426950408889634f, -126.0f);
    float z = t + 12582912.0f;
    float fl = z - 12582912.0f;
    float f = t - fl;
    int n = __float_as_int(z) - 0x4B400000;
    float p = 1.3333558146e-3f;
    p = fmaf(p, f, 9.6181291056e-3f);
    p = fmaf(p, f, 5.5504108664e-2f);
    p = fmaf(p, f, 2.4022650696e-1f);
    p = fmaf(p, f, 6.9314718056e-1f);
    p = fmaf(p, f, 1.0f);
    return __int_as_float((n + 127) << 23) * p;
}

// ---------------- smem layout (dynamic, li_tile) ----------------
#define OFF_DTAB  0                     // 512 floats (2048B)
#define OFF_QIDX  2048                  // 64 ints
#define OFF_KIDX  2304                  // 128 ints
#define OFF_EPI   2816                  // m/l/r [4][64] floats (3072B)
#define OFF_Q0    6144                  // 2 x 8KB Q stage
#define OFF_K0    22528                 // 2 x 16KB K stage
#define SMEM_TOTAL 55296                // 54KB -> 3 CTAs/SM

// ---------------- kernel P: norm (with replicated compaction) + dtab ----------
__global__ __launch_bounds__(512) void prep(const float* __restrict__ qin,
                                            const float* __restrict__ kin,
                                            const int* __restrict__ qm,
                                            const int* __restrict__ kmm,
                                            const float* __restrict__ alpha_p) {
    const int blk = blockIdx.x;
    const int tid = threadIdx.x;
    if (blk == 24 * NGRP) {
        float ar = alpha_p[0];
        float alpha = ar > 0.f ? ar : 0.01f * ar;    // leaky_relu
        g_dtab[tid] = __expf(-alpha * (float)tid);
        return;
    }
    const int b = blk / NGRP;
    const int g = blk % NGRP;
    const int which = b >= 8;
    const int i = which ? b - 8 : b;
    const int* msk = which ? kmm + i * SEQ_ : qm + i * SEQ_;

    __shared__ int idxS[SEQ_];
    __shared__ int wcnt[16], wpre[16];
    __shared__ int cntS;
    const int warp = tid >> 5, lane = tid & 31;

    int v = msk[tid] != 0;
    unsigned bl = __ballot_sync(0xffffffffu, v);
    if (lane == 0) wcnt[warp] = __popc(bl);
    __syncthreads();
    if (tid == 0) {
        int s = 0;
        #pragma unroll
        for (int w = 0; w < 16; w++) { wpre[w] = s; s += wcnt[w]; }
        cntS = s;
    }
    __syncthreads();
    if (v) idxS[wpre[warp] + __popc(bl & ((1u << lane) - 1))] = tid;
    __syncthreads();
    const int cnt = cntS;

    if (g == 0) {
        if (tid < cnt) (which ? g_kidx : g_qidx)[i * SEQ_ + tid] = idxS[tid];
        if (tid == 0)  (which ? g_kcnt : g_qcnt)[i] = cnt;
    }

    const int sp = g * 16 + warp;
    if (sp >= cnt) return;
    const float* in = (which ? kin : qin) + (long)i * SEQ_ * HID_;
    __half* outb = (which ? g_kn : g_qn) + (long)i * SEQ_ * HID_;

    const float4* src = (const float4*)(in + (long)idxS[sp] * HID_);
    float4 vv[6];
    float s = 0.f;
    #pragma unroll
    for (int k = 0; k < 6; k++) {
        vv[k] = src[lane + 32 * k];
        s += vv[k].x * vv[k].x + vv[k].y * vv[k].y + vv[k].z * vv[k].z + vv[k].w * vv[k].w;
    }
    #pragma unroll
    for (int o = 16; o; o >>= 1) s += __shfl_xor_sync(0xffffffffu, s, o);
    float sc = 1.0f / fmaxf(sqrtf(s), 1e-12f);
    uint2* dst = (uint2*)(outb + (long)sp * HID_);
    #pragma unroll
    for (int k = 0; k < 6; k++) {
        __half2 h0 = __floats2half2_rn(vv[k].x * sc, vv[k].y * sc);
        __half2 h1 = __floats2half2_rn(vv[k].z * sc, vv[k].w * sc);
        uint2 u;
        u.x = *reinterpret_cast<uint32_t*>(&h0);
        u.y = *reinterpret_cast<uint32_t*>(&h1);
        dst[lane + 32 * k] = u;
    }
}

// fragment loader for one k-step (R16 tiling: 2 A-LDSM + 2 B-LDSM)
#define LOAD_FRAGS(ksv, afrX, bfrX) do { \
    _Pragma("unroll") \
    for (int mt = 0; mt < 2; mt++) { \
        int rowA = wr * 32 + mt * 16 + (lane & 7) + ((lane >> 3) & 1) * 8; \
        int kcol = (ksv) * 16 + (lane >> 4) * 8; \
        uint32_t ad = qbase + SWZ((uint32_t)(rowA * 128 + kcol * 2)); \
        LDSM4((afrX)[mt][0], (afrX)[mt][1], (afrX)[mt][2], (afrX)[mt][3], ad); \
    } \
    _Pragma("unroll") \
    for (int np = 0; np < 2; np++) { \
        int nrow = wc * 32 + (np * 2 + (lane >> 4)) * 8 + (lane & 7); \
        int kcol = (ksv) * 16 + ((lane >> 3) & 1) * 8; \
        uint32_t ad = kbase + SWZ((uint32_t)(nrow * 128 + kcol * 2)); \
        LDSM4((bfrX)[np * 2][0], (bfrX)[np * 2][1], \
              (bfrX)[np * 2 + 1][0], (bfrX)[np * 2 + 1][1], ad); \
    } \
} while (0)

// ---------------- kernel 1: one (pair, 64-row stile, 128-col ktile) per CTA ----
// 8 warps 2(M)x4(N), warp tile 32x32, 3 CTAs/SM, reg-pipelined fragment loads.
__global__ __launch_bounds__(256, 3) void li_tile() {
    extern __shared__ char sm[];
    const uint32_t sb = smem_u32(sm);
    const int tid = threadIdx.x, wid = tid >> 5, lane = tid & 31;
    const int wr = wid >> 2, wc = wid & 3;
    const int pair = blockIdx.z;
    const int i = pair >> 4, j = pair & 15;
    const int s0 = blockIdx.y * 64;
    const int t0 = blockIdx.x * 128;

    const int qcnt = g_qcnt[i];
    const int kcnt = g_kcnt[j];
    if (s0 >= qcnt || t0 >= kcnt) return;

    float* dtab  = (float*)(sm + OFF_DTAB);
    int*   qidxS = (int*)(sm + OFF_QIDX);
    int*   kidxS = (int*)(sm + OFF_KIDX);
    float* epi   = (float*)(sm + OFF_EPI);

    int qr[2], kr[4];
    #pragma unroll
    for (int it = 0; it < 2; it++)
        qr[it] = min(s0 + ((tid + it * 256) >> 3), qcnt - 1);
    #pragma unroll
    for (int it = 0; it < 4; it++)
        kr[it] = min(t0 + ((tid + it * 256) >> 3), kcnt - 1);
    const int seg = tid & 7;

    const uint4* qsrc = (const uint4*)g_qn + (long)i * SEQ_ * 96;
    const uint4* ksrc = (const uint4*)g_kn + (long)j * SEQ_ * 96;

    // stage chunk 0
    {
        uint32_t qb = sb + OFF_Q0, kb = sb + OFF_K0;
        #pragma unroll
        for (int it = 0; it < 2; it++) {
            int r = (tid + it * 256) >> 3;
            cp16(qb + SWZ((uint32_t)(r * 128 + seg * 16)), qsrc + qr[it] * 96 + seg);
        }
        #pragma unroll
        for (int it = 0; it < 4; it++) {
            int r = (tid + it * 256) >> 3;
            cp16(kb + SWZ((uint32_t)(r * 128 + seg * 16)), ksrc + kr[it] * 96 + seg);
        }
        CP_COMMIT();
    }

    {
        dtab[tid]       = g_dtab[tid];
        dtab[tid + 256] = g_dtab[tid + 256];
        if (tid < 64)  qidxS[tid] = g_qidx[i * SEQ_ + min(s0 + tid, qcnt - 1)];
        if (tid < 128) kidxS[tid] = g_kidx[j * SEQ_ + min(t0 + tid, kcnt - 1)];
    }

    float acc[2][4][4];
    #pragma unroll
    for (int a = 0; a < 2; a++)
        #pragma unroll
        for (int b = 0; b < 4; b++)
            #pragma unroll
            for (int e = 0; e < 4; e++) acc[a][b][e] = 0.f;
    __syncthreads();

    for (int kc = 0; kc < 12; kc++) {
        const int b = kc & 1;
        CP_WAIT0();
        __syncthreads();
        if (kc < 11) {
            uint32_t qb = sb + OFF_Q0 + (b ^ 1) * 8192;
            uint32_t kb = sb + OFF_K0 + (b ^ 1) * 16384;
            #pragma unroll
            for (int it = 0; it < 2; it++) {
                int r = (tid + it * 256) >> 3;
                cp16(qb + SWZ((uint32_t)(r * 128 + seg * 16)), qsrc + qr[it] * 96 + (kc + 1) * 8 + seg);
            }
            #pragma unroll
            for (int it = 0; it < 4; it++) {
                int r = (tid + it * 256) >> 3;
                cp16(kb + SWZ((uint32_t)(r * 128 + seg * 16)), ksrc + kr[it] * 96 + (kc + 1) * 8 + seg);
            }
            CP_COMMIT();
        }
        const uint32_t qbase = sb + OFF_Q0 + b * 8192;
        const uint32_t kbase = sb + OFF_K0 + b * 16384;

        // register double-buffered fragment pipeline (headroom exists at this tile size)
        uint32_t afr[2][2][4], bfr[2][4][2];
        LOAD_FRAGS(0, afr[0], bfr[0]);
        #pragma unroll
        for (int ks = 0; ks < 4; ks++) {
            const int cur = ks & 1;
            if (ks < 3) LOAD_FRAGS(ks + 1, afr[cur ^ 1], bfr[cur ^ 1]);
            #pragma unroll
            for (int mt = 0; mt < 2; mt++)
                #pragma unroll
                for (int nt = 0; nt < 4; nt++)
                    MMA16816(acc[mt][nt], afr[cur][mt], bfr[cur][nt]);
        }
    }

    // ---- per-tile softmax partials ----
    float* mS = epi;          // [4][64]
    float* lS = epi + 256;
    float* rS = epi + 512;

    #pragma unroll
    for (int mt = 0; mt < 2; mt++) {
        #pragma unroll
        for (int h = 0; h < 2; h++) {
            int rowl = wr * 32 + mt * 16 + h * 8 + (lane >> 2);
            int sO = qidxS[rowl];
            float lg[8];
            float bm = NEG_BIG;
            #pragma unroll
            for (int nt = 0; nt < 4; nt++) {
                #pragma unroll
                for (int e = 0; e < 2; e++) {
                    int tl = wc * 32 + nt * 8 + (lane & 3) * 2 + e;
                    float c = acc[mt][nt][h * 2 + e];
                    float w = dtab[abs(sO - kidxS[tl])];
                    float L = (t0 + tl < kcnt) ? c * w : NEG_BIG;
                    lg[nt * 2 + e] = L;
                    bm = fmaxf(bm, L);
                }
            }
            bm = fmaxf(bm, __shfl_xor_sync(0xffffffffu, bm, 1));
            bm = fmaxf(bm, __shfl_xor_sync(0xffffffffu, bm, 2));
            float lv = 0.f, rv = 0.f;
            #pragma unroll
            for (int nt = 0; nt < 4; nt++) {
                #pragma unroll
                for (int e = 0; e < 2; e++) {
                    float p = fexp(lg[nt * 2 + e] - bm);
                    lv += p;
                    rv += p * acc[mt][nt][h * 2 + e];
                }
            }
            lv += __shfl_xor_sync(0xffffffffu, lv, 1);
            lv += __shfl_xor_sync(0xffffffffu, lv, 2);
            rv += __shfl_xor_sync(0xffffffffu, rv, 1);
            rv += __shfl_xor_sync(0xffffffffu, rv, 2);
            if ((lane & 3) == 0) {
                mS[wc * 64 + rowl] = bm;
                lS[wc * 64 + rowl] = lv;
                rS[wc * 64 + rowl] = rv;
            }
        }
    }
    __syncthreads();

    if (tid < 64) {
        float m0 = mS[tid],       m1 = mS[64 + tid];
        float m2 = mS[128 + tid], m3 = mS[192 + tid];
        float ma = fmaxf(m0, m1), mb = fmaxf(m2, m3);
        float mm = fmaxf(ma, mb);
        float e0 = fexp(m0 - mm), e1 = fexp(m1 - mm);
        float e2 = fexp(m2 - mm), e3 = fexp(m3 - mm);
        float ll = lS[tid] * e0 + lS[64 + tid] * e1 + lS[128 + tid] * e2 + lS[192 + tid] * e3;
        float rr = rS[tid] * e0 + rS[64 + tid] * e1 + rS[128 + tid] * e2 + rS[192 + tid] * e3;
        long o = ((((long)pair * STILES + blockIdx.y) * KTILES + blockIdx.x) << 6) + tid;
        g_m[o] = mm; g_l[o] = ll; g_r[o] = rr;
    }
}

// ---------------- kernel 2: merge + rowsum -> out[B,KB] ----------------
__global__ __launch_bounds__(512) void li_combine(float* __restrict__ out) {
    const int pair = blockIdx.x;
    const int i = pair >> 4, j = pair & 15;
    const int qcnt = g_qcnt[i], kcnt = g_kcnt[j];
    const int ktiles = (kcnt + 127) >> 7;
    const int tid = threadIdx.x;
    const int st = tid >> 6, row = tid & 63;
    const int lane = tid & 31;

    float val = 0.f;
    if (st * 64 + row < qcnt) {
        long base = ((((long)pair * STILES + st) * KTILES) << 6) + row;
        float m[4], l[4], r[4];
        #pragma unroll
        for (int kt = 0; kt < KTILES; kt++) {
            bool v = kt < ktiles;
            long o = base + ((long)kt << 6);
            m[kt] = v ? g_m[o] : NEG_BIG;
            l[kt] = v ? g_l[o] : 0.f;
            r[kt] = v ? g_r[o] : 0.f;
        }
        float ma = fmaxf(m[0], m[1]);
        float ea0 = fexp(m[0] - ma), ea1 = fexp(m[1] - ma);
        float la = l[0] * ea0 + l[1] * ea1;
        float ra = r[0] * ea0 + r[1] * ea1;
        float mb = fmaxf(m[2], m[3]);
        float eb0 = fexp(m[2] - mb), eb1 = fexp(m[3] - mb);
        float lb = l[2] * eb0 + l[3] * eb1;
        float rb = r[2] * eb0 + r[3] * eb1;
        float mf = fmaxf(ma, mb);
        float ef0 = fexp(ma - mf), ef1 = fexp(mb - mf);
        float lf = la * ef0 + lb * ef1;
        float rf = ra * ef0 + rb * ef1;
        val = (lf > 0.f) ? rf / lf : 0.f;
    }
    #pragma unroll
    for (int o = 16; o; o >>= 1) val += __shfl_xor_sync(0xffffffffu, val, o);
    __shared__ float w16[16];
    if (lane == 0) w16[tid >> 5] = val;
    __syncthreads();
    if (tid < 16) {
        float v = w16[tid];
        #pragma unroll
        for (int o = 8; o; o >>= 1) v += __shfl_xor_sync(0xffffu, v, o);
        if (tid == 0) out[pair] = v;
    }
}

// ---------------- launch ----------------
extern "C" void kernel_launch(void* const* d_in, const int* in_sizes, int n_in,
                              void* d_out, int out_size) {
    const float* qe    = (const float*)d_in[0];   // [8,512,768]
    const float* ke    = (const float*)d_in[1];   // [16,512,768]
    const float* alpha = (const float*)d_in[2];   // scalar
    const int*   qm    = (const int*)d_in[3];     // [8,512]
    const int*   kmm   = (const int*)d_in[4];     // [16,512]
    float* out = (float*)d_out;                   // [8,16]

    cudaFuncSetAttribute(li_tile, cudaFuncAttributeMaxDynamicSharedMemorySize, SMEM_TOTAL);

    prep<<<24 * NGRP + 1, 512>>>(qe, ke, qm, kmm, alpha);
    dim3 grid(KTILES, STILES, NPAIR);
    li_tile<<<grid, 256, SMEM_TOTAL>>>();
    li_combine<<<NPAIR, 512>>>(out);
}